// round 13
// baseline (speedup 1.0000x reference)
#include <cuda_runtime.h>
#include <math.h>

#define HW   65536
#define IMG  6291456          // 96*65536
#define NPIX 25165824         // 4*96*65536
#define SCALE 0.17677669529663687f

typedef unsigned long long ull;

// Full-batch buffers. g_Q / g_K are reused as D0 / D1 scratch after attention.
static __device__ __align__(16) float g_V[NPIX];
static __device__ __align__(16) float g_aV[NPIX];
static __device__ __align__(16) float g_Q[NPIX];
static __device__ __align__(16) float g_K[NPIX];
static __device__ __align__(16) float g_attn[NPIX];
static __device__ __align__(16) float g_bias[3 * 64 * 64];

// ---- f32x2 packed helpers (attention) --------------------------------------
__device__ __forceinline__ ull pk(float x) {
    ull r; asm("mov.b64 %0, {%1, %1};" : "=l"(r) : "f"(x)); return r;
}
__device__ __forceinline__ ull pk2(float lo, float hi) {
    ull r; asm("mov.b64 %0, {%1, %2};" : "=l"(r) : "f"(lo), "f"(hi)); return r;
}
__device__ __forceinline__ float2 upk(ull v) {
    float2 f; asm("mov.b64 {%0, %1}, %2;" : "=f"(f.x), "=f"(f.y) : "l"(v)); return f;
}
__device__ __forceinline__ ull fma2(ull a, ull b, ull c) {
    ull r; asm("fma.rn.f32x2 %0, %1, %2, %3;" : "=l"(r) : "l"(a), "l"(b), "l"(c)); return r;
}
__device__ __forceinline__ ull mul2(ull a, ull b) {
    ull r; asm("mul.rn.f32x2 %0, %1, %2;" : "=l"(r) : "l"(a), "l"(b)); return r;
}

// ---- mma.sync helpers -------------------------------------------------------
__device__ __forceinline__ unsigned smem_u32(const void* p) {
    unsigned a;
    asm("{ .reg .u64 t; cvta.to.shared.u64 t, %1; cvt.u32.u64 %0, t; }" : "=r"(a) : "l"(p));
    return a;
}
__device__ __forceinline__ void ldsm4(unsigned* r, unsigned addr) {
    asm volatile("ldmatrix.sync.aligned.m8n8.x4.shared.b16 {%0,%1,%2,%3}, [%4];"
                 : "=r"(r[0]), "=r"(r[1]), "=r"(r[2]), "=r"(r[3]) : "r"(addr));
}
__device__ __forceinline__ void mma_bf16(float* c, const unsigned* a, unsigned b0, unsigned b1) {
    asm volatile(
        "mma.sync.aligned.m16n8k16.row.col.f32.bf16.bf16.f32 "
        "{%0,%1,%2,%3}, {%4,%5,%6,%7}, {%8,%9}, {%0,%1,%2,%3};"
        : "+f"(c[0]), "+f"(c[1]), "+f"(c[2]), "+f"(c[3])
        : "r"(a[0]), "r"(a[1]), "r"(a[2]), "r"(a[3]), "r"(b0), "r"(b1));
}
// pack 2 floats -> bf16x2 {lo=v0, hi=v1}
__device__ __forceinline__ unsigned cvt2(float v0, float v1) {
    unsigned r; asm("cvt.rn.bf16x2.f32 %0, %1, %2;" : "=r"(r) : "f"(v1), "f"(v0)); return r;
}

// swizzled smem byte offsets: row stride 384 B, 16B-window XOR by (row&7)
__device__ __forceinline__ int physA(int px, int kb) { return px * 384 + (kb ^ ((px & 7) << 4)); }
__device__ __forceinline__ int physB(int o,  int kb) { return o  * 384 + (kb ^ ((o  & 7) << 4)); }

#define SM_A 0
#define SM_B 49152
#define SM_BIAS 86016
#define SM_TOTAL 87424

// ---------------------------------------------------------------------------
// K1: relative-position bias MLP
// ---------------------------------------------------------------------------
__device__ __forceinline__ float sgnlog(int d) {
    float l = log1pf(fabsf((float)d));
    return d < 0 ? -l : l;
}

__global__ void bias_kernel(const float* __restrict__ mw1, const float* __restrict__ mb1,
                            const float* __restrict__ mw2, const float* __restrict__ mb2) {
    int t = blockIdx.x * 256 + threadIdx.x;
    if (t >= 4096) return;
    int i = t >> 6, j = t & 63;
    float r0 = sgnlog((i >> 3) - (j >> 3));
    float r1 = sgnlog((i & 7) - (j & 7));
    float a0 = 0.f, a1 = 0.f, a2 = 0.f;
    for (int h = 0; h < 256; h++) {
        float hid = fmaf(r0, mw1[h], fmaf(r1, mw1[256 + h], mb1[h]));
        hid = fmaxf(hid, 0.f);
        a0 = fmaf(hid, mw2[h * 3 + 0], a0);
        a1 = fmaf(hid, mw2[h * 3 + 1], a1);
        a2 = fmaf(hid, mw2[h * 3 + 2], a2);
    }
    g_bias[t]        = a0 + mb2[0];
    g_bias[4096 + t] = a1 + mb2[1];
    g_bias[8192 + t] = a2 + mb2[2];
}

// ---------------------------------------------------------------------------
// Shared conv building blocks (mma.sync bf16 split-2)
// ---------------------------------------------------------------------------
__device__ __forceinline__ void conv_a_convert(char* raw, const float* inb, int wid, int lane) {
    int c2 = lane >> 3, pxl = lane & 7;   // 4 c-pairs x 8 px per warp-iter
    #pragma unroll 4
    for (int it = 0; it < 24; it++) {
        int g = it * 8 + wid;             // 0..191
        int po = g & 15, cq = g >> 4;     // 16 px-octets x 12 c-quads
        int c = cq * 8 + c2 * 2;
        int px = po * 8 + pxl;
        float v0 = inb[c * HW + px];
        float v1 = inb[(c + 1) * HW + px];
        unsigned hi = cvt2(v0, v1);
        float h0 = __uint_as_float(hi << 16);
        float h1 = __uint_as_float(hi & 0xffff0000u);
        unsigned lo = cvt2(v0 - h0, v1 - h1);
        *(unsigned*)(raw + SM_A + physA(px, c * 2))       = hi;
        *(unsigned*)(raw + SM_A + physA(px, 192 + c * 2)) = lo;
    }
}

__device__ __forceinline__ void conv_b_convert(char* raw, const float* w, int tid) {
    for (int l = tid; l < 4608; l += 256) {
        int o = l / 48, cp = l - (l / 48) * 48;
        int c = cp * 2;
        float2 wv = upk(*(const ull*)(w + o * 96 + c));
        unsigned hi = cvt2(wv.x, wv.y);
        float h0 = __uint_as_float(hi << 16);
        float h1 = __uint_as_float(hi & 0xffff0000u);
        unsigned lo = cvt2(wv.x - h0, wv.y - h1);
        *(unsigned*)(raw + SM_B + physB(o, c * 2))       = hi;
        *(unsigned*)(raw + SM_B + physB(o, 192 + c * 2)) = lo;
    }
}

// mainloop + epilogue. Caller must __syncthreads() before (B ready).
__device__ __forceinline__ void conv_mma_epi(
    char* raw, const float* s_bias_p, float* outb, float scl,
    int wid, int lane)
{
    unsigned sA32 = smem_u32(raw + SM_A);
    unsigned sB32 = smem_u32(raw + SM_B);
    int wm = wid >> 1, wn = wid & 1;
    int gr = lane & 7, gi = lane >> 3;
    int swz = gr << 4;
    int kextA = (gi >> 1) << 4;   // bytes
    int kextB = (gi & 1) << 4;
    int aRow[2], bRow[3];
    #pragma unroll
    for (int tm = 0; tm < 2; tm++)
        aRow[tm] = (wm * 32 + tm * 16 + gr + (gi & 1) * 8) * 384;
    #pragma unroll
    for (int tp = 0; tp < 3; tp++)
        bRow[tp] = (wn * 48 + tp * 16 + gr + (gi >> 1) * 8) * 384;

    float c[2][6][4];
    #pragma unroll
    for (int tm = 0; tm < 2; tm++)
        #pragma unroll
        for (int tn = 0; tn < 6; tn++)
            #pragma unroll
            for (int q = 0; q < 4; q++) c[tm][tn][q] = 0.f;

    #pragma unroll
    for (int t = 0; t < 3; t++) {
        int kaB = (t == 2) ? 192 : 0;     // A lo for term 2
        int kbB = (t == 1) ? 192 : 0;     // B lo for term 1
        #pragma unroll
        for (int ks = 0; ks < 6; ks++) {
            unsigned aF[2][4], bF[3][4];
            int ka = kaB + ks * 32;
            int kb = kbB + ks * 32;
            #pragma unroll
            for (int tm = 0; tm < 2; tm++)
                ldsm4(aF[tm], sA32 + aRow[tm] + ((ka + kextA) ^ swz));
            #pragma unroll
            for (int tp = 0; tp < 3; tp++)
                ldsm4(bF[tp], sB32 + bRow[tp] + ((kb + kextB) ^ swz));
            #pragma unroll
            for (int tm = 0; tm < 2; tm++)
                #pragma unroll
                for (int tn = 0; tn < 6; tn++) {
                    int tp = tn >> 1, r0 = (tn & 1) * 2;
                    mma_bf16(c[tm][tn], aF[tm], bF[tp][r0], bF[tp][r0 + 1]);
                }
        }
    }
    __syncthreads();   // all ldsm done -> B buffer reusable by caller

    int pr = lane >> 2, oc = (lane & 3) * 2;
    #pragma unroll
    for (int tm = 0; tm < 2; tm++) {
        int pxr = wm * 32 + tm * 16 + pr;
        #pragma unroll
        for (int tn = 0; tn < 6; tn++) {
            int o0 = wn * 48 + tn * 8 + oc;
            float b0 = s_bias_p[o0], b1 = s_bias_p[o0 + 1];
            outb[o0 * HW + pxr]            = (c[tm][tn][0] + b0) * scl;
            outb[(o0 + 1) * HW + pxr]      = (c[tm][tn][1] + b1) * scl;
            outb[o0 * HW + pxr + 8]        = (c[tm][tn][2] + b0) * scl;
            outb[(o0 + 1) * HW + pxr + 8]  = (c[tm][tn][3] + b1) * scl;
        }
    }
}

// ---------------------------------------------------------------------------
// K2a: phased V/Q/K conv1x1 — one A conversion, three B phases. grid 2048.
// ---------------------------------------------------------------------------
__global__ __launch_bounds__(256, 2)
void conv3_kernel(const float* __restrict__ vision,
                  const float* __restrict__ wv,  const float* __restrict__ bv,
                  const float* __restrict__ wqk, const float* __restrict__ bqk) {
    extern __shared__ __align__(16) char raw[];
    float* s_bias = (float*)(raw + SM_BIAS);

    int tid = threadIdx.x;
    int wid = tid >> 5, lane = tid & 31;
    int bx = blockIdx.x;
    int b = bx >> 9, px0 = (bx & 511) << 7;
    const float* inb = vision + b * IMG + px0;
    int gbase = b * IMG + px0;

    // all three bias vectors up front
    if (tid < 96)        s_bias[tid]        = bv[tid];
    else if (tid < 192)  s_bias[tid]        = bqk[tid - 96];        // Q bias at +96
    if (tid < 96)        s_bias[192 + tid]  = bqk[96 + tid];        // K bias at +192

    conv_a_convert(raw, inb, wid, lane);

    // phase 0: V
    conv_b_convert(raw, wv, tid);
    __syncthreads();
    conv_mma_epi(raw, s_bias, g_V + gbase, 1.0f, wid, lane);

    // phase 1: Q (pre-scaled)
    conv_b_convert(raw, wqk, tid);
    __syncthreads();
    conv_mma_epi(raw, s_bias + 96, g_Q + gbase, SCALE, wid, lane);

    // phase 2: K
    conv_b_convert(raw, wqk + 9216, tid);
    __syncthreads();
    conv_mma_epi(raw, s_bias + 192, g_K + gbase, 1.0f, wid, lane);
}

// ---------------------------------------------------------------------------
// K2b: generic single-job conv1x1.
// ---------------------------------------------------------------------------
struct ConvJob { const float* in; const float* w; const float* bias; float* out; float scale; };

__global__ __launch_bounds__(256, 2)
void conv_kernel(ConvJob j) {
    extern __shared__ __align__(16) char raw[];
    float* s_bias = (float*)(raw + SM_BIAS);

    int tid = threadIdx.x;
    int wid = tid >> 5, lane = tid & 31;
    int bx = blockIdx.x;
    int b = bx >> 9, px0 = (bx & 511) << 7;
    const float* inb = j.in + b * IMG + px0;

    if (tid < 96) s_bias[tid] = j.bias[tid];
    conv_a_convert(raw, inb, wid, lane);
    conv_b_convert(raw, j.w, tid);
    __syncthreads();
    conv_mma_epi(raw, s_bias, j.out + b * IMG + px0, j.scale, wid, lane);
}

// ---------------------------------------------------------------------------
// K3: window attention — one thread per (head, row); one barrier.
// In-place softmax (scores stay packed in acc[] — no p[64], no spills).
// smem floats: s_q[3][64*33] | s_k ull[3][32*33] | s_v[3][64*34] = 76800 B
// ---------------------------------------------------------------------------
__global__ __launch_bounds__(192, 2)
void attn_kernel() {
    extern __shared__ float sm[];
    float* s_q = sm;                      // [h][n*33+d]
    ull*   s_k = (ull*)(sm + 6336);       // [h][d*33+m2]
    float* s_v = sm + 12672;              // [h][m*34+d]

    int tid = threadIdx.x;
    int blk = blockIdx.x;
    int b = blk >> 10, wy = (blk >> 5) & 31, wx = blk & 31;
    int pixoff = b * IMG + wy * 2048 + wx * 8;

    for (int l = tid; l < 3072; l += 192) {
        int hh = l >> 10;
        int r = l & 1023;
        int d = r >> 5, n2 = r & 31;
        int ga = pixoff + (hh * 32 + d) * HW + (n2 >> 2) * 256 + (n2 & 3) * 2;
        float2 q = upk(*(const ull*)(g_Q + ga));
        s_q[hh * 2112 + (2 * n2) * 33 + d] = q.x;
        s_q[hh * 2112 + (2 * n2 + 1) * 33 + d] = q.y;
        s_k[hh * 1056 + d * 33 + n2] = *(const ull*)(g_K + ga);
        float2 v = upk(*(const ull*)(g_V + ga));
        s_v[hh * 2176 + (2 * n2) * 34 + d] = v.x;
        s_v[hh * 2176 + (2 * n2 + 1) * 34 + d] = v.y;
    }
    __syncthreads();

    int h = tid >> 6, n = tid & 63;
    const float* qrow = s_q + h * 2112 + n * 33;
    const ull*   kh   = s_k + h * 1056;
    const float* vh   = s_v + h * 2176;

    // ---- S row = q . K^T + bias (bias as accumulator init) ----
    ull acc[32];
    {
        const ull* bias2 = (const ull*)(g_bias + h * 4096 + n * 64);
        #pragma unroll
        for (int m2 = 0; m2 < 32; m2++) acc[m2] = bias2[m2];
    }
    #pragma unroll 4
    for (int d = 0; d < 32; d++) {
        ull qd = pk(qrow[d]);
        const ull* krow = kh + d * 33;
        #pragma unroll
        for (int m2 = 0; m2 < 32; m2++) acc[m2] = fma2(qd, krow[m2], acc[m2]);
    }

    // ---- softmax in place: scores never leave acc[] ----
    float mx = -1e30f;
    #pragma unroll
    for (int m2 = 0; m2 < 32; m2++) {
        float2 f = upk(acc[m2]);
        mx = fmaxf(mx, fmaxf(f.x, f.y));
    }
    float sum = 0.f;
    #pragma unroll
    for (int m2 = 0; m2 < 32; m2++) {
        float2 f = upk(acc[m2]);
        f.x = __expf(f.x - mx);
        f.y = __expf(f.y - mx);
        sum += f.x + f.y;
        acc[m2] = pk2(f.x, f.y);
    }
    float rinv = 1.f / sum;

    // ---- O row = (1/sum) * p . V  (p unpacked from acc on the fly) ----
    ull oacc[16];
    #pragma unroll
    for (int d2 = 0; d2 < 16; d2++) oacc[d2] = 0ull;
    #pragma unroll 2
    for (int m2 = 0; m2 < 32; m2++) {
        float2 f = upk(acc[m2]);
        ull pm0 = pk(f.x), pm1 = pk(f.y);
        const float* v0 = vh + (2 * m2) * 34;
        const float* v1 = v0 + 34;
        #pragma unroll
        for (int d2 = 0; d2 < 16; d2++)
            oacc[d2] = fma2(pm0, *(const ull*)(v0 + 2 * d2), oacc[d2]);
        #pragma unroll
        for (int d2 = 0; d2 < 16; d2++)
            oacc[d2] = fma2(pm1, *(const ull*)(v1 + 2 * d2), oacc[d2]);
    }
    ull rr = pk(rinv);
    float* ob = g_attn + pixoff + (n >> 3) * 256 + (n & 7);
    #pragma unroll
    for (int d2 = 0; d2 < 16; d2++) {
        float2 f = upk(mul2(oacc[d2], rr));
        ob[(h * 32 + 2 * d2) * HW] = f.x;
        ob[(h * 32 + 2 * d2 + 1) * HW] = f.y;
    }
}

// ---------------------------------------------------------------------------
// K4: single-z depthwise 5x5 + bias + attn -> D. grid 6144 per z.
// ---------------------------------------------------------------------------
__global__ __launch_bounds__(256)
void dwz_kernel(const float* __restrict__ Vp, const float* __restrict__ wD,
                const float* __restrict__ bD, float* __restrict__ Dp) {
    extern __shared__ float st[];
    float* s_wd = st + 5280;           // halo [20][264] then weights

    int bx = blockIdx.x;               // 6144 = 16 * 96 * 4
    int yt = bx & 15;
    int v = bx >> 4;
    int c = v % 96, b = v / 96;
    int y0 = yt << 4;
    int tid = threadIdx.x;
    int chan = b * IMG + c * HW;
    const float* Vc = Vp + chan;

    for (int l = tid; l < 5200; l += 256) {
        int r = l / 260, q = l - r * 260;
        int yy = y0 + r - 2; yy = yy < 0 ? -yy : (yy > 255 ? 510 - yy : yy);
        int xx = q - 2;      xx = xx < 0 ? -xx : (xx > 255 ? 510 - xx : xx);
        st[r * 264 + q] = Vc[yy * 256 + xx];
    }
    if (tid < 25) s_wd[tid] = wD[c * 25 + tid];
    __syncthreads();

    int col = tid;
    float w[25];
    #pragma unroll
    for (int k = 0; k < 25; k++) w[k] = s_wd[k];
    float bias = __ldg(&bD[c]);

    float acc[16];
    const float* ab = g_attn + chan + y0 * 256 + col;
    #pragma unroll
    for (int r = 0; r < 16; r++) acc[r] = bias + ab[r * 256];

    #pragma unroll
    for (int rr = 0; rr < 20; rr++) {
        float xv[5];
        #pragma unroll
        for (int dx = 0; dx < 5; dx++) xv[dx] = st[rr * 264 + col + dx];
        #pragma unroll
        for (int dy = 0; dy < 5; dy++) {
            int r = rr - dy;
            if (r >= 0 && r < 16) {
                #pragma unroll
                for (int dx = 0; dx < 5; dx++)
                    acc[r] = fmaf(xv[dx], w[dy * 5 + dx], acc[r]);
            }
        }
    }

    float* db = Dp + chan + y0 * 256 + col;
    #pragma unroll
    for (int r = 0; r < 16; r++)
        db[r * 256] = acc[r];
}

// ---------------------------------------------------------------------------
extern "C" void kernel_launch(void* const* d_in, const int* in_sizes, int n_in,
                              void* d_out, int out_size) {
    const float* vision     = (const float*)d_in[0];
    const float* ass_vision = (const float*)d_in[1];
    const float* wv   = (const float*)d_in[2];
    const float* bv   = (const float*)d_in[3];
    const float* wav  = (const float*)d_in[4];
    const float* bav  = (const float*)d_in[5];
    const float* wqk  = (const float*)d_in[6];
    const float* bqk  = (const float*)d_in[7];
    // d_in[8..9]: waqk/baqk dead (reference bug: aaw unused, ass_attn_out = attn_out)
    const float* wdw  = (const float*)d_in[10];
    const float* bdw  = (const float*)d_in[11];
    const float* wdwa = (const float*)d_in[12];
    const float* bdwa = (const float*)d_in[13];
    const float* wp   = (const float*)d_in[14];
    const float* bp   = (const float*)d_in[15];
    const float* wpa  = (const float*)d_in[16];
    const float* bpa  = (const float*)d_in[17];
    const float* mw1  = (const float*)d_in[18];
    const float* mb1  = (const float*)d_in[19];
    const float* mw2  = (const float*)d_in[20];
    const float* mb2  = (const float*)d_in[21];
    float* out = (float*)d_out;

    float *pV, *paV, *pQ, *pK;
    cudaGetSymbolAddress((void**)&pV,  g_V);
    cudaGetSymbolAddress((void**)&paV, g_aV);
    cudaGetSymbolAddress((void**)&pQ,  g_Q);
    cudaGetSymbolAddress((void**)&pK,  g_K);

    const int SMEM_ATTN = 19200 * 4;   // 76800
    const int SMEM_DW   = 5312 * 4;    // 21248
    cudaFuncSetAttribute(conv3_kernel, cudaFuncAttributeMaxDynamicSharedMemorySize, SM_TOTAL);
    cudaFuncSetAttribute(conv_kernel,  cudaFuncAttributeMaxDynamicSharedMemorySize, SM_TOTAL);
    cudaFuncSetAttribute(attn_kernel,  cudaFuncAttributeMaxDynamicSharedMemorySize, SMEM_ATTN);
    cudaFuncSetAttribute(dwz_kernel,   cudaFuncAttributeMaxDynamicSharedMemorySize, SMEM_DW);

    // one-time stream/event infrastructure (host-side, no device memory)
    static cudaStream_t s2 = nullptr;
    static cudaEvent_t evFork = nullptr, evAttn = nullptr, evEnd = nullptr;
    if (!s2) {
        cudaStreamCreateWithFlags(&s2, cudaStreamNonBlocking);
        cudaEventCreateWithFlags(&evFork, cudaEventDisableTiming);
        cudaEventCreateWithFlags(&evAttn, cudaEventDisableTiming);
        cudaEventCreateWithFlags(&evEnd,  cudaEventDisableTiming);
    }

    // fork: s2 starts from the capture-stream front
    cudaEventRecord(evFork, 0);
    cudaStreamWaitEvent(s2, evFork, 0);

    // ---- s2 chain: jaV (independent) ----
    ConvJob jaV = { ass_vision, wav, bav, paV, 1.0f };
    conv_kernel<<<2048, 256, SM_TOTAL, s2>>>(jaV);

    // ---- main chain: bias -> conv3 (V,Q,K) -> attn ----
    bias_kernel<<<16, 256>>>(mw1, mb1, mw2, mb2);
    conv3_kernel<<<2048, 256, SM_TOTAL>>>(vision, wv, bv, wqk, bqk);
    attn_kernel<<<4096, 192, SMEM_ATTN>>>();
    cudaEventRecord(evAttn, 0);

    // ---- s2 chain continues: dw1 (aV + attn -> g_K) -> P1 ----
    cudaStreamWaitEvent(s2, evAttn, 0);
    dwz_kernel<<<6144, 256, SMEM_DW, s2>>>(paV, wdwa, bdwa, pK);
    ConvJob jP1 = { pK, wpa, bpa, out + NPIX, 1.0f };
    conv_kernel<<<2048, 256, SM_TOTAL, s2>>>(jP1);
    cudaEventRecord(evEnd, s2);

    // ---- main chain: dw0 (V + attn -> g_Q) -> P0 ----
    dwz_kernel<<<6144, 256, SMEM_DW>>>(pV, wdw, bdw, pQ);
    ConvJob jP0 = { pQ, wp, bp, out, 1.0f };
    conv_kernel<<<2048, 256, SM_TOTAL>>>(jP0);

    // join s2 back into the capture stream
    cudaStreamWaitEvent(0, evEnd, 0);
}

// round 14
// speedup vs baseline: 1.1592x; 1.1592x over previous
#include <cuda_runtime.h>
#include <math.h>

#define HW   65536
#define IMG  6291456          // 96*65536
#define NPIX 25165824         // 4*96*65536
#define SCALE 0.17677669529663687f

typedef unsigned long long ull;

// Full-batch buffers. g_Q / g_K are reused as D0 / D1 scratch after attention.
static __device__ __align__(16) float g_V[NPIX];
static __device__ __align__(16) float g_aV[NPIX];
static __device__ __align__(16) float g_Q[NPIX];
static __device__ __align__(16) float g_K[NPIX];
static __device__ __align__(16) float g_attn[NPIX];
static __device__ __align__(16) float g_bias[3 * 64 * 64];

// ---- f32x2 packed helpers (attention) --------------------------------------
__device__ __forceinline__ ull pk(float x) {
    ull r; asm("mov.b64 %0, {%1, %1};" : "=l"(r) : "f"(x)); return r;
}
__device__ __forceinline__ float2 upk(ull v) {
    float2 f; asm("mov.b64 {%0, %1}, %2;" : "=f"(f.x), "=f"(f.y) : "l"(v)); return f;
}
__device__ __forceinline__ ull fma2(ull a, ull b, ull c) {
    ull r; asm("fma.rn.f32x2 %0, %1, %2, %3;" : "=l"(r) : "l"(a), "l"(b), "l"(c)); return r;
}
__device__ __forceinline__ ull add2(ull a, ull b) {
    ull r; asm("add.rn.f32x2 %0, %1, %2;" : "=l"(r) : "l"(a), "l"(b)); return r;
}
__device__ __forceinline__ ull mul2(ull a, ull b) {
    ull r; asm("mul.rn.f32x2 %0, %1, %2;" : "=l"(r) : "l"(a), "l"(b)); return r;
}

// ---- mma.sync helpers -------------------------------------------------------
__device__ __forceinline__ unsigned smem_u32(const void* p) {
    unsigned a;
    asm("{ .reg .u64 t; cvta.to.shared.u64 t, %1; cvt.u32.u64 %0, t; }" : "=r"(a) : "l"(p));
    return a;
}
__device__ __forceinline__ void ldsm4(unsigned* r, unsigned addr) {
    asm volatile("ldmatrix.sync.aligned.m8n8.x4.shared.b16 {%0,%1,%2,%3}, [%4];"
                 : "=r"(r[0]), "=r"(r[1]), "=r"(r[2]), "=r"(r[3]) : "r"(addr));
}
__device__ __forceinline__ void mma_bf16(float* c, const unsigned* a, unsigned b0, unsigned b1) {
    asm volatile(
        "mma.sync.aligned.m16n8k16.row.col.f32.bf16.bf16.f32 "
        "{%0,%1,%2,%3}, {%4,%5,%6,%7}, {%8,%9}, {%0,%1,%2,%3};"
        : "+f"(c[0]), "+f"(c[1]), "+f"(c[2]), "+f"(c[3])
        : "r"(a[0]), "r"(a[1]), "r"(a[2]), "r"(a[3]), "r"(b0), "r"(b1));
}
// pack 2 floats -> bf16x2 {lo=v0, hi=v1}
__device__ __forceinline__ unsigned cvt2(float v0, float v1) {
    unsigned r; asm("cvt.rn.bf16x2.f32 %0, %1, %2;" : "=r"(r) : "f"(v1), "f"(v0)); return r;
}

// swizzled smem byte offsets: row stride 384 B, 16B-window XOR by (row&7)
__device__ __forceinline__ int physA(int px, int kb) { return px * 384 + (kb ^ ((px & 7) << 4)); }
__device__ __forceinline__ int physB(int o,  int kb) { return o  * 384 + (kb ^ ((o  & 7) << 4)); }

#define SM_A 0
#define SM_B 49152
#define SM_BIAS 86016
#define SM_TOTAL 87424

// ---------------------------------------------------------------------------
// K1: relative-position bias MLP
// ---------------------------------------------------------------------------
__device__ __forceinline__ float sgnlog(int d) {
    float l = log1pf(fabsf((float)d));
    return d < 0 ? -l : l;
}

__global__ void bias_kernel(const float* __restrict__ mw1, const float* __restrict__ mb1,
                            const float* __restrict__ mw2, const float* __restrict__ mb2) {
    int t = blockIdx.x * 256 + threadIdx.x;
    if (t >= 4096) return;
    int i = t >> 6, j = t & 63;
    float r0 = sgnlog((i >> 3) - (j >> 3));
    float r1 = sgnlog((i & 7) - (j & 7));
    float a0 = 0.f, a1 = 0.f, a2 = 0.f;
    for (int h = 0; h < 256; h++) {
        float hid = fmaf(r0, mw1[h], fmaf(r1, mw1[256 + h], mb1[h]));
        hid = fmaxf(hid, 0.f);
        a0 = fmaf(hid, mw2[h * 3 + 0], a0);
        a1 = fmaf(hid, mw2[h * 3 + 1], a1);
        a2 = fmaf(hid, mw2[h * 3 + 2], a2);
    }
    g_bias[t]        = a0 + mb2[0];
    g_bias[4096 + t] = a1 + mb2[1];
    g_bias[8192 + t] = a2 + mb2[2];
}

// ---------------------------------------------------------------------------
// Shared conv building blocks (mma.sync bf16 split-2)
// ---------------------------------------------------------------------------
__device__ __forceinline__ void conv_a_convert(char* raw, const float* inb, int wid, int lane) {
    int c2 = lane >> 3, pxl = lane & 7;   // 4 c-pairs x 8 px per warp-iter
    #pragma unroll 4
    for (int it = 0; it < 24; it++) {
        int g = it * 8 + wid;             // 0..191
        int po = g & 15, cq = g >> 4;     // 16 px-octets x 12 c-quads
        int c = cq * 8 + c2 * 2;
        int px = po * 8 + pxl;
        float v0 = inb[c * HW + px];
        float v1 = inb[(c + 1) * HW + px];
        unsigned hi = cvt2(v0, v1);
        float h0 = __uint_as_float(hi << 16);
        float h1 = __uint_as_float(hi & 0xffff0000u);
        unsigned lo = cvt2(v0 - h0, v1 - h1);
        *(unsigned*)(raw + SM_A + physA(px, c * 2))       = hi;
        *(unsigned*)(raw + SM_A + physA(px, 192 + c * 2)) = lo;
    }
}

__device__ __forceinline__ void conv_b_convert(char* raw, const float* w, int tid) {
    for (int l = tid; l < 4608; l += 256) {
        int o = l / 48, cp = l - (l / 48) * 48;
        int c = cp * 2;
        float2 wv = upk(*(const ull*)(w + o * 96 + c));
        unsigned hi = cvt2(wv.x, wv.y);
        float h0 = __uint_as_float(hi << 16);
        float h1 = __uint_as_float(hi & 0xffff0000u);
        unsigned lo = cvt2(wv.x - h0, wv.y - h1);
        *(unsigned*)(raw + SM_B + physB(o, c * 2))       = hi;
        *(unsigned*)(raw + SM_B + physB(o, 192 + c * 2)) = lo;
    }
}

// mainloop + epilogue. Caller must __syncthreads() before (B ready).
__device__ __forceinline__ void conv_mma_epi(
    char* raw, const float* s_bias_p, float* outb, float scl,
    int wid, int lane)
{
    unsigned sA32 = smem_u32(raw + SM_A);
    unsigned sB32 = smem_u32(raw + SM_B);
    int wm = wid >> 1, wn = wid & 1;
    int gr = lane & 7, gi = lane >> 3;
    int swz = gr << 4;
    int kextA = (gi >> 1) << 4;   // bytes
    int kextB = (gi & 1) << 4;
    int aRow[2], bRow[3];
    #pragma unroll
    for (int tm = 0; tm < 2; tm++)
        aRow[tm] = (wm * 32 + tm * 16 + gr + (gi & 1) * 8) * 384;
    #pragma unroll
    for (int tp = 0; tp < 3; tp++)
        bRow[tp] = (wn * 48 + tp * 16 + gr + (gi >> 1) * 8) * 384;

    float c[2][6][4];
    #pragma unroll
    for (int tm = 0; tm < 2; tm++)
        #pragma unroll
        for (int tn = 0; tn < 6; tn++)
            #pragma unroll
            for (int q = 0; q < 4; q++) c[tm][tn][q] = 0.f;

    #pragma unroll
    for (int t = 0; t < 3; t++) {
        int kaB = (t == 2) ? 192 : 0;     // A lo for term 2
        int kbB = (t == 1) ? 192 : 0;     // B lo for term 1
        #pragma unroll
        for (int ks = 0; ks < 6; ks++) {
            unsigned aF[2][4], bF[3][4];
            int ka = kaB + ks * 32;
            int kb = kbB + ks * 32;
            #pragma unroll
            for (int tm = 0; tm < 2; tm++)
                ldsm4(aF[tm], sA32 + aRow[tm] + ((ka + kextA) ^ swz));
            #pragma unroll
            for (int tp = 0; tp < 3; tp++)
                ldsm4(bF[tp], sB32 + bRow[tp] + ((kb + kextB) ^ swz));
            #pragma unroll
            for (int tm = 0; tm < 2; tm++)
                #pragma unroll
                for (int tn = 0; tn < 6; tn++) {
                    int tp = tn >> 1, r0 = (tn & 1) * 2;
                    mma_bf16(c[tm][tn], aF[tm], bF[tp][r0], bF[tp][r0 + 1]);
                }
        }
    }
    __syncthreads();   // all ldsm done -> B buffer reusable by caller

    int pr = lane >> 2, oc = (lane & 3) * 2;
    #pragma unroll
    for (int tm = 0; tm < 2; tm++) {
        int pxr = wm * 32 + tm * 16 + pr;
        #pragma unroll
        for (int tn = 0; tn < 6; tn++) {
            int o0 = wn * 48 + tn * 8 + oc;
            float b0 = s_bias_p[o0], b1 = s_bias_p[o0 + 1];
            outb[o0 * HW + pxr]            = (c[tm][tn][0] + b0) * scl;
            outb[(o0 + 1) * HW + pxr]      = (c[tm][tn][1] + b1) * scl;
            outb[o0 * HW + pxr + 8]        = (c[tm][tn][2] + b0) * scl;
            outb[(o0 + 1) * HW + pxr + 8]  = (c[tm][tn][3] + b1) * scl;
        }
    }
}

// ---------------------------------------------------------------------------
// K2a: phased V/Q/K conv1x1 — one A conversion, three B phases. grid 2048.
// ---------------------------------------------------------------------------
__global__ __launch_bounds__(256, 2)
void conv3_kernel(const float* __restrict__ vision,
                  const float* __restrict__ wv,  const float* __restrict__ bv,
                  const float* __restrict__ wqk, const float* __restrict__ bqk) {
    extern __shared__ __align__(16) char raw[];
    float* s_bias = (float*)(raw + SM_BIAS);

    int tid = threadIdx.x;
    int wid = tid >> 5, lane = tid & 31;
    int bx = blockIdx.x;
    int b = bx >> 9, px0 = (bx & 511) << 7;
    const float* inb = vision + b * IMG + px0;
    int gbase = b * IMG + px0;

    // all three bias vectors up front
    if (tid < 96)        s_bias[tid]        = bv[tid];
    else if (tid < 192)  s_bias[tid]        = bqk[tid - 96];        // Q bias at +96
    if (tid < 96)        s_bias[192 + tid]  = bqk[96 + tid];        // K bias at +192

    conv_a_convert(raw, inb, wid, lane);

    // phase 0: V
    conv_b_convert(raw, wv, tid);
    __syncthreads();
    conv_mma_epi(raw, s_bias, g_V + gbase, 1.0f, wid, lane);

    // phase 1: Q (pre-scaled)
    conv_b_convert(raw, wqk, tid);
    __syncthreads();
    conv_mma_epi(raw, s_bias + 96, g_Q + gbase, SCALE, wid, lane);

    // phase 2: K
    conv_b_convert(raw, wqk + 9216, tid);
    __syncthreads();
    conv_mma_epi(raw, s_bias + 192, g_K + gbase, 1.0f, wid, lane);
}

// ---------------------------------------------------------------------------
// K2b: generic single-job conv1x1.
// ---------------------------------------------------------------------------
struct ConvJob { const float* in; const float* w; const float* bias; float* out; float scale; };

__global__ __launch_bounds__(256, 2)
void conv_kernel(ConvJob j) {
    extern __shared__ __align__(16) char raw[];
    float* s_bias = (float*)(raw + SM_BIAS);

    int tid = threadIdx.x;
    int wid = tid >> 5, lane = tid & 31;
    int bx = blockIdx.x;
    int b = bx >> 9, px0 = (bx & 511) << 7;
    const float* inb = j.in + b * IMG + px0;

    if (tid < 96) s_bias[tid] = j.bias[tid];
    conv_a_convert(raw, inb, wid, lane);
    conv_b_convert(raw, j.w, tid);
    __syncthreads();
    conv_mma_epi(raw, s_bias, j.out + b * IMG + px0, j.scale, wid, lane);
}

// ---------------------------------------------------------------------------
// K3: window attention — TWO threads per (head, row): thread = (h, n, half).
// half owns column-pairs m2 = 2j+half (j<16) and d-range [half*16, half*16+16).
// Pairwise shuffle combine; acc 16 ull, oacc 16 ull -> ~84 regs -> occ 2x384.
// smem floats: s_q[3][64*33] | s_k ull[3][32*33] | s_v[3][64*34] = 76800 B
// ---------------------------------------------------------------------------
__global__ __launch_bounds__(384, 2)
void attn_kernel() {
    extern __shared__ float sm[];
    float* s_q = sm;                      // [h][n*33+d]
    ull*   s_k = (ull*)(sm + 6336);       // [h][d*33+m2]
    float* s_v = sm + 12672;              // [h][m*34+d]

    int tid = threadIdx.x;
    int blk = blockIdx.x;
    int b = blk >> 10, wy = (blk >> 5) & 31, wx = blk & 31;
    int pixoff = b * IMG + wy * 2048 + wx * 8;

    for (int l = tid; l < 3072; l += 384) {
        int hh = l >> 10;
        int r = l & 1023;
        int d = r >> 5, n2 = r & 31;
        int ga = pixoff + (hh * 32 + d) * HW + (n2 >> 2) * 256 + (n2 & 3) * 2;
        float2 q = upk(*(const ull*)(g_Q + ga));
        s_q[hh * 2112 + (2 * n2) * 33 + d] = q.x;
        s_q[hh * 2112 + (2 * n2 + 1) * 33 + d] = q.y;
        s_k[hh * 1056 + d * 33 + n2] = *(const ull*)(g_K + ga);
        float2 v = upk(*(const ull*)(g_V + ga));
        s_v[hh * 2176 + (2 * n2) * 34 + d] = v.x;
        s_v[hh * 2176 + (2 * n2 + 1) * 34 + d] = v.y;
    }
    __syncthreads();

    int h = tid >> 7;                 // head
    int r = tid & 127;
    int n = r >> 1, half = r & 1;     // half: partner = lane^1
    const float* qrow = s_q + h * 2112 + n * 33;
    const ull*   kh   = s_k + h * 1056 + half;
    const float* vh   = s_v + h * 2176;

    // ---- S half-row: acc[j] = scores for m2 = 2j+half (cols 4j+2half, +1) ----
    ull acc[16];
    {
        const ull* bias2 = (const ull*)(g_bias + h * 4096 + n * 64) + half;
        #pragma unroll
        for (int jj = 0; jj < 16; jj++) acc[jj] = bias2[2 * jj];
    }
    #pragma unroll 4
    for (int d = 0; d < 32; d++) {
        ull qd = pk(qrow[d]);
        const ull* krow = kh + d * 33;
        #pragma unroll
        for (int jj = 0; jj < 16; jj++) acc[jj] = fma2(qd, krow[2 * jj], acc[jj]);
    }

    // ---- softmax across the pair ----
    float mx = -1e30f;
    #pragma unroll
    for (int jj = 0; jj < 16; jj++) {
        float2 f = upk(acc[jj]);
        mx = fmaxf(mx, fmaxf(f.x, f.y));
    }
    mx = fmaxf(mx, __shfl_xor_sync(0xffffffffu, mx, 1));
    float p[32];
    float sum = 0.f;
    #pragma unroll
    for (int jj = 0; jj < 16; jj++) {
        float2 f = upk(acc[jj]);
        p[2 * jj]     = __expf(f.x - mx);
        p[2 * jj + 1] = __expf(f.y - mx);
        sum += p[2 * jj] + p[2 * jj + 1];
    }
    sum += __shfl_xor_sync(0xffffffffu, sum, 1);
    float rinv = 1.f / sum;

    // ---- PV over my 32 columns; oacc = [my 16 d | other 16 d] ----
    const float* vmine  = vh + half * 16;
    const float* vother = vh + (1 - half) * 16;
    ull oacc[16];
    #pragma unroll
    for (int d2 = 0; d2 < 16; d2++) oacc[d2] = 0ull;
    #pragma unroll 2
    for (int jj = 0; jj < 16; jj++) {
        int m0 = 4 * jj + 2 * half;
        ull pm0 = pk(p[2 * jj]), pm1 = pk(p[2 * jj + 1]);
        const float* a0 = vmine  + m0 * 34;
        const float* b0 = vother + m0 * 34;
        #pragma unroll
        for (int d2 = 0; d2 < 8; d2++) {
            oacc[d2]     = fma2(pm0, *(const ull*)(a0 + 2 * d2), oacc[d2]);
            oacc[8 + d2] = fma2(pm0, *(const ull*)(b0 + 2 * d2), oacc[8 + d2]);
        }
        #pragma unroll
        for (int d2 = 0; d2 < 8; d2++) {
            oacc[d2]     = fma2(pm1, *(const ull*)(a0 + 34 + 2 * d2), oacc[d2]);
            oacc[8 + d2] = fma2(pm1, *(const ull*)(b0 + 34 + 2 * d2), oacc[8 + d2]);
        }
    }

    // ---- combine with partner: partner's oacc[8+k] is MY d-half ----
    #pragma unroll
    for (int k = 0; k < 8; k++) {
        ull recv = __shfl_xor_sync(0xffffffffu, oacc[8 + k], 1);
        oacc[k] = add2(oacc[k], recv);
    }

    // ---- scale + store my 16 d's ----
    ull rr = pk(rinv);
    float* obd = g_attn + pixoff + (n >> 3) * 256 + (n & 7) + (h * 32 + half * 16) * HW;
    #pragma unroll
    for (int k = 0; k < 8; k++) {
        float2 f = upk(mul2(oacc[k], rr));
        obd[(2 * k) * HW]     = f.x;
        obd[(2 * k + 1) * HW] = f.y;
    }
}

// ---------------------------------------------------------------------------
// K4: single-z depthwise 5x5 + bias + attn -> D. grid 6144 per z.
// ---------------------------------------------------------------------------
__global__ __launch_bounds__(256)
void dwz_kernel(const float* __restrict__ Vp, const float* __restrict__ wD,
                const float* __restrict__ bD, float* __restrict__ Dp) {
    extern __shared__ float st[];
    float* s_wd = st + 5280;           // halo [20][264] then weights

    int bx = blockIdx.x;               // 6144 = 16 * 96 * 4
    int yt = bx & 15;
    int v = bx >> 4;
    int c = v % 96, b = v / 96;
    int y0 = yt << 4;
    int tid = threadIdx.x;
    int chan = b * IMG + c * HW;
    const float* Vc = Vp + chan;

    for (int l = tid; l < 5200; l += 256) {
        int r = l / 260, q = l - r * 260;
        int yy = y0 + r - 2; yy = yy < 0 ? -yy : (yy > 255 ? 510 - yy : yy);
        int xx = q - 2;      xx = xx < 0 ? -xx : (xx > 255 ? 510 - xx : xx);
        st[r * 264 + q] = Vc[yy * 256 + xx];
    }
    if (tid < 25) s_wd[tid] = wD[c * 25 + tid];
    __syncthreads();

    int col = tid;
    float w[25];
    #pragma unroll
    for (int k = 0; k < 25; k++) w[k] = s_wd[k];
    float bias = __ldg(&bD[c]);

    float acc[16];
    const float* ab = g_attn + chan + y0 * 256 + col;
    #pragma unroll
    for (int r = 0; r < 16; r++) acc[r] = bias + ab[r * 256];

    #pragma unroll
    for (int rr = 0; rr < 20; rr++) {
        float xv[5];
        #pragma unroll
        for (int dx = 0; dx < 5; dx++) xv[dx] = st[rr * 264 + col + dx];
        #pragma unroll
        for (int dy = 0; dy < 5; dy++) {
            int r = rr - dy;
            if (r >= 0 && r < 16) {
                #pragma unroll
                for (int dx = 0; dx < 5; dx++)
                    acc[r] = fmaf(xv[dx], w[dy * 5 + dx], acc[r]);
            }
        }
    }

    float* db = Dp + chan + y0 * 256 + col;
    #pragma unroll
    for (int r = 0; r < 16; r++)
        db[r * 256] = acc[r];
}

// ---------------------------------------------------------------------------
extern "C" void kernel_launch(void* const* d_in, const int* in_sizes, int n_in,
                              void* d_out, int out_size) {
    const float* vision     = (const float*)d_in[0];
    const float* ass_vision = (const float*)d_in[1];
    const float* wv   = (const float*)d_in[2];
    const float* bv   = (const float*)d_in[3];
    const float* wav  = (const float*)d_in[4];
    const float* bav  = (const float*)d_in[5];
    const float* wqk  = (const float*)d_in[6];
    const float* bqk  = (const float*)d_in[7];
    // d_in[8..9]: waqk/baqk dead (reference bug: aaw unused, ass_attn_out = attn_out)
    const float* wdw  = (const float*)d_in[10];
    const float* bdw  = (const float*)d_in[11];
    const float* wdwa = (const float*)d_in[12];
    const float* bdwa = (const float*)d_in[13];
    const float* wp   = (const float*)d_in[14];
    const float* bp   = (const float*)d_in[15];
    const float* wpa  = (const float*)d_in[16];
    const float* bpa  = (const float*)d_in[17];
    const float* mw1  = (const float*)d_in[18];
    const float* mb1  = (const float*)d_in[19];
    const float* mw2  = (const float*)d_in[20];
    const float* mb2  = (const float*)d_in[21];
    float* out = (float*)d_out;

    float *pV, *paV, *pQ, *pK;
    cudaGetSymbolAddress((void**)&pV,  g_V);
    cudaGetSymbolAddress((void**)&paV, g_aV);
    cudaGetSymbolAddress((void**)&pQ,  g_Q);
    cudaGetSymbolAddress((void**)&pK,  g_K);

    const int SMEM_ATTN = 19200 * 4;   // 76800
    const int SMEM_DW   = 5312 * 4;    // 21248
    cudaFuncSetAttribute(conv3_kernel, cudaFuncAttributeMaxDynamicSharedMemorySize, SM_TOTAL);
    cudaFuncSetAttribute(conv_kernel,  cudaFuncAttributeMaxDynamicSharedMemorySize, SM_TOTAL);
    cudaFuncSetAttribute(attn_kernel,  cudaFuncAttributeMaxDynamicSharedMemorySize, SMEM_ATTN);
    cudaFuncSetAttribute(dwz_kernel,   cudaFuncAttributeMaxDynamicSharedMemorySize, SMEM_DW);

    // one-time stream/event infrastructure (host-side, no device memory)
    static cudaStream_t s2 = nullptr;
    static cudaEvent_t evFork = nullptr, evAttn = nullptr, evEnd = nullptr;
    if (!s2) {
        cudaStreamCreateWithFlags(&s2, cudaStreamNonBlocking);
        cudaEventCreateWithFlags(&evFork, cudaEventDisableTiming);
        cudaEventCreateWithFlags(&evAttn, cudaEventDisableTiming);
        cudaEventCreateWithFlags(&evEnd,  cudaEventDisableTiming);
    }

    // fork: s2 starts from the capture-stream front
    cudaEventRecord(evFork, 0);
    cudaStreamWaitEvent(s2, evFork, 0);

    // ---- s2 chain: jaV (independent) ----
    ConvJob jaV = { ass_vision, wav, bav, paV, 1.0f };
    conv_kernel<<<2048, 256, SM_TOTAL, s2>>>(jaV);

    // ---- main chain: bias -> conv3 (V,Q,K) -> attn ----
    bias_kernel<<<16, 256>>>(mw1, mb1, mw2, mb2);
    conv3_kernel<<<2048, 256, SM_TOTAL>>>(vision, wv, bv, wqk, bqk);
    attn_kernel<<<4096, 384, SMEM_ATTN>>>();
    cudaEventRecord(evAttn, 0);

    // ---- s2 chain continues: dw1 (aV + attn -> g_K) -> P1 ----
    cudaStreamWaitEvent(s2, evAttn, 0);
    dwz_kernel<<<6144, 256, SMEM_DW, s2>>>(paV, wdwa, bdwa, pK);
    ConvJob jP1 = { pK, wpa, bpa, out + NPIX, 1.0f };
    conv_kernel<<<2048, 256, SM_TOTAL, s2>>>(jP1);
    cudaEventRecord(evEnd, s2);

    // ---- main chain: dw0 (V + attn -> g_Q) -> P0 ----
    dwz_kernel<<<6144, 256, SMEM_DW>>>(pV, wdw, bdw, pQ);
    ConvJob jP0 = { pQ, wp, bp, out, 1.0f };
    conv_kernel<<<2048, 256, SM_TOTAL>>>(jP0);

    // join s2 back into the capture stream
    cudaStreamWaitEvent(0, evEnd, 0);
}